// round 9
// baseline (speedup 1.0000x reference)
#include <cuda_runtime.h>
#include <cuda_fp16.h>

#define NCFG 21

__constant__ int c_kh[NCFG] = {74,60,49,93,76,62, 148,120,98,186,152,124,
                               235,192,156,296,241,197,373,304,248};
__constant__ int c_kw[NCFG] = {49,60,74,62,76,93, 98,120,148,124,152,186,
                               156,192,235,197,241,296,248,304,373};
__constant__ int c_off[NCFG] = {0,3626,7226,10852,16618,22394,
                                28160,42664,57064,71568,94632,117736,
                                140800,177460,214324,250984,309296,367377,
                                425689,518193,610609};
// total area = 703113 pixels; scratch: [cfg][bk(32)][pixel], half4 packed in float2
#define TOTAL_AGG 22499616
__device__ float2 g_aggh[TOTAL_AGG];   // 180 MB

// x padded to float4 with guard margins
#define XN 1605632
#define GUARD 1024
__device__ float4 g_x4g[XN + 2 * GUARD];

// Tap tables
__device__ float4 g_tyw[NCFG][224];
__device__ int4   g_tyo[NCFG][224];   // row offsets premultiplied by kw
__device__ float4 g_txw[NCFG][224];
__device__ int4   g_txo[NCFG][224];   // column offsets (float2 units)

// ---------------- packed f32x2 helpers ----------------
__device__ __forceinline__ unsigned long long f2pack(float lo, float hi) {
    unsigned long long r;
    asm("mov.b64 %0, {%1, %2};" : "=l"(r) : "f"(lo), "f"(hi));
    return r;
}
__device__ __forceinline__ void funpack(unsigned long long v, float& lo, float& hi) {
    asm("mov.b64 {%0, %1}, %2;" : "=f"(lo), "=f"(hi) : "l"(v));
}
__device__ __forceinline__ void ffma2(unsigned long long& d,
                                      unsigned long long a, unsigned long long b) {
    asm("fma.rn.f32x2 %0, %1, %2, %0;" : "+l"(d) : "l"(a), "l"(b));
}

__device__ __forceinline__ float2 pack_h4(float a, float b, float c) {
    union { float2 f; __half2 h[2]; } u;
    u.h[0] = __floats2half2_rn(a, b);
    u.h[1] = __floats2half2_rn(c, 0.0f);
    return u.f;
}

// ---------------------------------------------------------------------------
// Prep: blocks [0,6272) pad x to float4; blocks [6272,6314) compute taps.
// ---------------------------------------------------------------------------
__global__ void prep_kernel(const float* __restrict__ x) {
    if (blockIdx.x < 6272) {
        const int idx = blockIdx.x * 256 + threadIdx.x;   // < XN exactly
        const float* p = x + (size_t)idx * 3;
        g_x4g[GUARD + idx] = make_float4(p[0], p[1], p[2], 0.0f);
        return;
    }
    const int bi  = blockIdx.x - 6272;      // 0..41
    const int cfg = bi % NCFG;
    const int dim = bi / NCFG;              // 0 = rows(kh), 1 = cols(kw)
    const int o   = threadIdx.x;
    if (o >= 224) return;

    const int n  = dim ? c_kw[cfg] : c_kh[cfg];
    const int kw = c_kw[cfg];

    const double ks = (n > 224) ? (double)n / 224.0 : 1.0;
    const double sf = ((double)o + 0.5) * (double)n / 224.0 - 0.5;
    const int NT = (n < 224) ? 2 : (2 * n) / 224 + 1;   // 2..4
    int lo = (int)ceil(sf - ks);

    double w[4];
    double tot = 0.0;
    for (int t = 0; t < 4; ++t) {
        double v = 0.0;
        if (t < NT) {
            int j = lo + t;
            if (j >= 0 && j < n) {
                v = 1.0 - fabs(sf - (double)j) / ks;
                if (v < 0.0) v = 0.0;
            }
        }
        w[t] = v;
        tot += v;
    }
    const double r = 1.0 / tot;

    float wf[4];
    int   of[4];
    for (int t = 0; t < 4; ++t) {
        wf[t] = (float)(w[t] * r);
        int j = lo + t;
        if (j < 0) j = 0;
        if (j > n - 1) j = n - 1;
        of[t] = dim ? j : j * kw;
    }
    if (dim == 0) {
        g_tyw[cfg][o] = make_float4(wf[0], wf[1], wf[2], wf[3]);
        g_tyo[cfg][o] = make_int4(of[0], of[1], of[2], of[3]);
    } else {
        g_txw[cfg][o] = make_float4(wf[0], wf[1], wf[2], wf[3]);
        g_txo[cfg][o] = make_int4(of[0], of[1], of[2], of[3]);
    }
}

// ---------------------------------------------------------------------------
// Kernel A for p3/p4 (unchanged R6 structure).
// ---------------------------------------------------------------------------
template<int S, int G, int A, int CFG0>
__global__ void agg_kernel(const float* __restrict__ wsrc) {
    const int cfg = CFG0 + blockIdx.z;
    const int kh = c_kh[cfg], kw = c_kw[cfg];
    const int area = kh * kw;
    if ((int)(blockIdx.x * blockDim.x) >= area) return;

    const int a = blockIdx.z;
    const int b = blockIdx.y;
    constexpr int G2 = G * G;

    __shared__ float4 sw4[G2];
    {
        float* swf = (float*)sw4;
        const float* wb = wsrc + (size_t)(b * A + a) * 4 * G2;
        for (int t = threadIdx.x; t < 4 * G2; t += blockDim.x) {
            const int gh = t >> 2, k = t & 3;
            swf[t] = wb[k * G2 + gh];
        }
    }
    __syncthreads();

    const int idx = blockIdx.x * blockDim.x + threadIdx.x;
    if (idx >= area) return;

    const int i = idx / kw;
    const int j = idx - i * kw;
    const int p0 = (kh - S + 1) >> 1;
    const int p1 = (kw - S + 1) >> 1;
    const int ri = i - p0;
    const int cj = j - p1;

    const int gmin = (ri >= 0) ? 0 : (-ri + S - 1) / S;
    const int gmax = min(G - 1, (447 - ri) / S);
    const int hmin = (cj >= 0) ? 0 : (-cj + S - 1) / S;
    const int hmax = min(G - 1, (447 - cj) / S);

    float a00=0,a01=0,a02=0, a10=0,a11=0,a12=0,
          a20=0,a21=0,a22=0, a30=0,a31=0,a32=0;

    for (int g = gmin; g <= gmax; ++g) {
        const float4* xrow = g_x4g + GUARD + (size_t)(b * 448 + g * S + ri) * 448 + cj;
        const float4* swg  = sw4 + g * G;
#pragma unroll 4
        for (int h = hmin; h <= hmax; ++h) {
            const float4 xv = __ldg(xrow + h * S);
            const float4 wv = swg[h];
            a00 += wv.x * xv.x; a01 += wv.x * xv.y; a02 += wv.x * xv.z;
            a10 += wv.y * xv.x; a11 += wv.y * xv.y; a12 += wv.y * xv.z;
            a20 += wv.z * xv.x; a21 += wv.z * xv.y; a22 += wv.z * xv.z;
            a30 += wv.w * xv.x; a31 += wv.w * xv.y; a32 += wv.w * xv.z;
        }
    }

    float2* dst = g_aggh + (size_t)32 * c_off[cfg] + (size_t)(b * 4) * area + idx;
    __stcs(dst,                    pack_h4(a00, a01, a02));
    __stcs(dst + (size_t)area,     pack_h4(a10, a11, a12));
    __stcs(dst + (size_t)2 * area, pack_h4(a20, a21, a22));
    __stcs(dst + (size_t)3 * area, pack_h4(a30, a31, a32));
}

// ---------------------------------------------------------------------------
// Specialized p5 agg (unchanged from R8).
// ---------------------------------------------------------------------------
__global__ void __launch_bounds__(256) agg5_kernel(const float* __restrict__ w5) {
    const int cfg = 12 + blockIdx.z;
    const int kh = c_kh[cfg], kw = c_kw[cfg];
    const int by = blockIdx.y;
    const int b  = by / 373;
    const int i  = by - b * 373;
    if (i >= kh) return;
    const int j0 = blockIdx.x * 256;
    if (j0 >= kw) return;

    __shared__ unsigned long long swp[64];
    {
        const int t = threadIdx.x;
        if (t < 64) {
            const int gh = t >> 2, k = t & 3;
            const float v = w5[((size_t)(b * 9 + blockIdx.z) * 4 + k) * 16 + gh];
            swp[t] = f2pack(v, v);
        }
    }
    __syncthreads();

    const int j = j0 + threadIdx.x;
    if (j >= kw) return;

    const int p0 = (kh - 127) >> 1;
    const int p1 = (kw - 127) >> 1;
    const int ri = i - p0;
    const int cj = j - p1;

    bool hv[4];
#pragma unroll
    for (int h = 0; h < 4; ++h)
        hv[h] = (unsigned)(cj + h * 128) <= 447u;

    unsigned long long acc01[4] = {0ull, 0ull, 0ull, 0ull};
    unsigned long long acc2p[4] = {0ull, 0ull, 0ull, 0ull};

    const float4* base = g_x4g + GUARD + ((long long)(b * 448) + ri) * 448 + cj;

#pragma unroll
    for (int g = 0; g < 4; ++g) {
        const int r = g * 128 + ri;
        if ((unsigned)r <= 447u) {
            float4 xv[4];
#pragma unroll
            for (int h = 0; h < 4; ++h)
                xv[h] = __ldg(base + g * (128 * 448) + h * 128);
#pragma unroll
            for (int h = 0; h < 4; ++h) {
                const float x0 = hv[h] ? xv[h].x : 0.0f;
                const float x1 = hv[h] ? xv[h].y : 0.0f;
                const float x2 = hv[h] ? xv[h].z : 0.0f;
                const unsigned long long x01 = f2pack(x0, x1);
                const unsigned long long x2w = f2pack(x2, 0.0f);
                const unsigned long long* wp = swp + (g * 4 + h) * 4;
#pragma unroll
                for (int k = 0; k < 4; ++k) {
                    const unsigned long long wk = wp[k];
                    ffma2(acc01[k], wk, x01);
                    ffma2(acc2p[k], wk, x2w);
                }
            }
        }
    }

    const int area = kh * kw;
    float2* dst = g_aggh + (size_t)32 * c_off[cfg] + (size_t)(b * 4) * area
                + (size_t)i * kw + j;
#pragma unroll
    for (int k = 0; k < 4; ++k) {
        float c0, c1, c2, cw;
        funpack(acc01[k], c0, c1);
        funpack(acc2p[k], c2, cw);
        __stcs(dst + (size_t)k * area, pack_h4(c0, c1, c2));
    }
}

// ---------------------------------------------------------------------------
// Kernel B: block-separable resize. Per (bk, oy-pair) block: for each cfg,
// vertical combine rows cooperatively (coalesced, HFMA2) into smem, then
// NC horizontal taps per thread from smem.
// ---------------------------------------------------------------------------
#define DO_CFG(CFG, AREA, OFF, NR, NC, KW) {                                   \
    const float2* base = g_aggh + (size_t)32 * OFF + (size_t)bk * AREA;        \
    _Pragma("unroll")                                                          \
    for (int cc = 0; cc < (KW + 223) / 224; ++cc) {                            \
        const int col = ox + cc * 224;                                         \
        if (col < KW) {                                                        \
            __half2 acc01 = __float2half2_rn(0.0f);                            \
            __half2 acc2  = acc01;                                             \
            _Pragma("unroll")                                                  \
            for (int r = 0; r < NR; ++r) {                                     \
                union { float2 f; __half2 h[2]; } u;                           \
                u.f = __ldg(base + s_yo[p][CFG * 4 + r] + col);                \
                const __half2 wyh = s_ywh[p][CFG * 4 + r];                     \
                acc01 = __hfma2(wyh, u.h[0], acc01);                           \
                acc2  = __hfma2(wyh, u.h[1], acc2);                            \
            }                                                                  \
            union { float2 f; __half2 h[2]; } ov;                              \
            ov.h[0] = acc01; ov.h[1] = acc2;                                   \
            sv[col] = ov.f;                                                    \
        }                                                                      \
    }                                                                          \
    __syncthreads();                                                           \
    {                                                                          \
        const float4 xw = g_txw[CFG][ox];                                      \
        const int4   xo = g_txo[CFG][ox];                                      \
        const float xwv[4] = {xw.x, xw.y, xw.z, xw.w};                         \
        const int   xov[4] = {xo.x, xo.y, xo.z, xo.w};                         \
        _Pragma("unroll")                                                      \
        for (int c = 0; c < NC; ++c) {                                         \
            union { float2 f; __half2 h[2]; } u;                               \
            u.f = sv[xov[c]];                                                  \
            const float2 lo = __half22float2(u.h[0]);                          \
            const float  hi = __low2float(u.h[1]);                            \
            a0 += xwv[c] * lo.x;                                               \
            a1 += xwv[c] * lo.y;                                               \
            a2 += xwv[c] * hi;                                                 \
        }                                                                      \
    }                                                                          \
    __syncthreads();                                                           \
}

__global__ void __launch_bounds__(224) resize_kernel(float* __restrict__ out) {
    const int bk = blockIdx.y;
    const int ox = threadIdx.x;

    __shared__ __half2 s_ywh[2][NCFG * 4];
    __shared__ int     s_yo[2][NCFG * 4];
    __shared__ float2  sv[384];

    for (int t = threadIdx.x; t < 2 * NCFG * 4; t += 224) {
        const int pp  = t / (NCFG * 4);
        const int q   = t - pp * (NCFG * 4);
        const int cfg = q >> 2, r = q & 3;
        const int oy  = 2 * blockIdx.x + pp;
        const float wy = ((const float*)&g_tyw[cfg][oy])[r];
        s_ywh[pp][q] = __float2half2_rn(wy);
        s_yo[pp][q]  = ((const int*)&g_tyo[cfg][oy])[r];
    }
    __syncthreads();

#pragma unroll 1
    for (int p = 0; p < 2; ++p) {
        const int oy = 2 * blockIdx.x + p;
        float a0 = 0.0f, a1 = 0.0f, a2 = 0.0f;

        DO_CFG( 0,  3626,      0, 2, 2,  49)
        DO_CFG( 1,  3600,   3626, 2, 2,  60)
        DO_CFG( 2,  3626,   7226, 2, 2,  74)
        DO_CFG( 3,  5766,  10852, 2, 2,  62)
        DO_CFG( 4,  5776,  16618, 2, 2,  76)
        DO_CFG( 5,  5766,  22394, 2, 2,  93)
        DO_CFG( 6, 14504,  28160, 2, 2,  98)
        DO_CFG( 7, 14400,  42664, 2, 2, 120)
        DO_CFG( 8, 14504,  57064, 2, 2, 148)
        DO_CFG( 9, 23064,  71568, 2, 2, 124)
        DO_CFG(10, 23104,  94632, 2, 2, 152)
        DO_CFG(11, 23064, 117736, 2, 2, 186)
        DO_CFG(12, 36660, 140800, 3, 2, 156)
        DO_CFG(13, 36864, 177460, 2, 2, 192)
        DO_CFG(14, 36660, 214324, 2, 3, 235)
        DO_CFG(15, 58312, 250984, 3, 2, 197)
        DO_CFG(16, 58081, 309296, 3, 3, 241)
        DO_CFG(17, 58312, 367377, 2, 3, 296)
        DO_CFG(18, 92504, 425689, 4, 3, 248)
        DO_CFG(19, 92416, 518193, 3, 3, 304)
        DO_CFG(20, 92504, 610609, 3, 4, 373)

        float* o = out + ((size_t)(bk * 224 + oy) * 224 + ox) * 3;
        o[0] = a0;
        o[1] = a1;
        o[2] = a2;
    }
}

// ---------------------------------------------------------------------------
extern "C" void kernel_launch(void* const* d_in, const int* in_sizes, int n_in,
                              void* d_out, int out_size) {
    const float* x  = (const float*)d_in[0];
    const float* w3 = (const float*)d_in[1];
    const float* w4 = (const float*)d_in[2];
    const float* w5 = (const float*)d_in[3];

    prep_kernel<<<6272 + 42, 256>>>(x);

    agg_kernel<32, 14, 6, 0><<<dim3(23, 8, 6), 256>>>(w3);
    agg_kernel<64, 7, 6, 6><<<dim3(91, 8, 6), 256>>>(w4);
    agg5_kernel<<<dim3(2, 8 * 373, 9), 256>>>(w5);

    dim3 gridB(112, 32);   // 2 oy rows per block
    resize_kernel<<<gridB, 224>>>((float*)d_out);
}

// round 11
// speedup vs baseline: 1.1813x; 1.1813x over previous
#include <cuda_runtime.h>
#include <cuda_fp16.h>

#define NCFG 21

__constant__ int c_kh[NCFG] = {74,60,49,93,76,62, 148,120,98,186,152,124,
                               235,192,156,296,241,197,373,304,248};
__constant__ int c_kw[NCFG] = {49,60,74,62,76,93, 98,120,148,124,152,186,
                               156,192,235,197,241,296,248,304,373};
__constant__ int c_off[NCFG] = {0,3626,7226,10852,16618,22394,
                                28160,42664,57064,71568,94632,117736,
                                140800,177460,214324,250984,309296,367377,
                                425689,518193,610609};
// total area = 703113 pixels; scratch: [cfg][bk(32)][pixel], half4 packed in float2
#define TOTAL_AGG 22499616
__device__ float2 g_aggh[TOTAL_AGG];   // 180 MB

// x in column-pitched layout: [row 0..3583][PITCH], data at cols [XOFF, XOFF+448),
// zero guard strips at [0,XOFF) and [XOFF+448, PITCH). Covers cj+h*S in [-123, 633].
#define PITCH 768
#define XOFF  128
#define XROWS 3584
__device__ float4 g_xp[XROWS * PITCH];   // 44 MB

// Tap tables
__device__ float4 g_tyw[NCFG][224];
__device__ int4   g_tyo[NCFG][224];   // row offsets premultiplied by kw
__device__ float4 g_txw[NCFG][224];
__device__ int4   g_txo[NCFG][224];   // column offsets (float2 units)

// ---------------- packed f32x2 helpers ----------------
__device__ __forceinline__ unsigned long long f2pack(float lo, float hi) {
    unsigned long long r;
    asm("mov.b64 %0, {%1, %2};" : "=l"(r) : "f"(lo), "f"(hi));
    return r;
}
__device__ __forceinline__ void funpack(unsigned long long v, float& lo, float& hi) {
    asm("mov.b64 {%0, %1}, %2;" : "=f"(lo), "=f"(hi) : "l"(v));
}
__device__ __forceinline__ void ffma2(unsigned long long& d,
                                      unsigned long long a, unsigned long long b) {
    asm("fma.rn.f32x2 %0, %1, %2, %0;" : "+l"(d) : "l"(a), "l"(b));
}

__device__ __forceinline__ float2 pack_h4(float a, float b, float c) {
    union { float2 f; __half2 h[2]; } u;
    u.h[0] = __floats2half2_rn(a, b);
    u.h[1] = __floats2half2_rn(c, 0.0f);
    return u.f;
}

// ---------------------------------------------------------------------------
// Prep: blocks [0,3584) fill one pitched row each (data + zero strips);
// blocks [3584,3626) compute taps. Block = 448 threads.
// ---------------------------------------------------------------------------
__global__ void __launch_bounds__(448) prep_kernel(const float* __restrict__ x) {
    if (blockIdx.x < XROWS) {
        const int rb = blockIdx.x;
        const int t  = threadIdx.x;
        float4* drow = g_xp + (size_t)rb * PITCH;
        const float4 z = make_float4(0.f, 0.f, 0.f, 0.f);
        if (t < 128)      drow[t] = z;                       // left strip
        else if (t < 320) drow[XOFF + 448 + (t - 128)] = z;  // right strip (192)
        const float* src = x + ((size_t)rb * 448 + t) * 3;
        drow[XOFF + t] = make_float4(src[0], src[1], src[2], 0.0f);
        return;
    }
    const int bi  = blockIdx.x - XROWS;     // 0..41
    const int cfg = bi % NCFG;
    const int dim = bi / NCFG;              // 0 = rows(kh), 1 = cols(kw)
    const int o   = threadIdx.x;
    if (o >= 224) return;

    const int n  = dim ? c_kw[cfg] : c_kh[cfg];
    const int kw = c_kw[cfg];

    const double ks = (n > 224) ? (double)n / 224.0 : 1.0;
    const double sf = ((double)o + 0.5) * (double)n / 224.0 - 0.5;
    const int NT = (n < 224) ? 2 : (2 * n) / 224 + 1;   // 2..4
    int lo = (int)ceil(sf - ks);

    double w[4];
    double tot = 0.0;
    for (int t = 0; t < 4; ++t) {
        double v = 0.0;
        if (t < NT) {
            int j = lo + t;
            if (j >= 0 && j < n) {
                v = 1.0 - fabs(sf - (double)j) / ks;
                if (v < 0.0) v = 0.0;
            }
        }
        w[t] = v;
        tot += v;
    }
    const double r = 1.0 / tot;

    float wf[4];
    int   of[4];
    for (int t = 0; t < 4; ++t) {
        wf[t] = (float)(w[t] * r);
        int j = lo + t;
        if (j < 0) j = 0;
        if (j > n - 1) j = n - 1;
        of[t] = dim ? j : j * kw;
    }
    if (dim == 0) {
        g_tyw[cfg][o] = make_float4(wf[0], wf[1], wf[2], wf[3]);
        g_tyo[cfg][o] = make_int4(of[0], of[1], of[2], of[3]);
    } else {
        g_txw[cfg][o] = make_float4(wf[0], wf[1], wf[2], wf[3]);
        g_txo[cfg][o] = make_int4(of[0], of[1], of[2], of[3]);
    }
}

// ---------------------------------------------------------------------------
// Kernel A for p3/p4 (R6 structure, pitched x addressing).
// ---------------------------------------------------------------------------
template<int S, int G, int A, int CFG0>
__global__ void agg_kernel(const float* __restrict__ wsrc) {
    const int cfg = CFG0 + blockIdx.z;
    const int kh = c_kh[cfg], kw = c_kw[cfg];
    const int area = kh * kw;
    if ((int)(blockIdx.x * blockDim.x) >= area) return;

    const int a = blockIdx.z;
    const int b = blockIdx.y;
    constexpr int G2 = G * G;

    __shared__ float4 sw4[G2];
    {
        float* swf = (float*)sw4;
        const float* wb = wsrc + (size_t)(b * A + a) * 4 * G2;
        for (int t = threadIdx.x; t < 4 * G2; t += blockDim.x) {
            const int gh = t >> 2, k = t & 3;
            swf[t] = wb[k * G2 + gh];
        }
    }
    __syncthreads();

    const int idx = blockIdx.x * blockDim.x + threadIdx.x;
    if (idx >= area) return;

    const int i = idx / kw;
    const int j = idx - i * kw;
    const int p0 = (kh - S + 1) >> 1;
    const int p1 = (kw - S + 1) >> 1;
    const int ri = i - p0;
    const int cj = j - p1;

    const int gmin = (ri >= 0) ? 0 : (-ri + S - 1) / S;
    const int gmax = min(G - 1, (447 - ri) / S);
    const int hmin = (cj >= 0) ? 0 : (-cj + S - 1) / S;
    const int hmax = min(G - 1, (447 - cj) / S);

    float a00=0,a01=0,a02=0, a10=0,a11=0,a12=0,
          a20=0,a21=0,a22=0, a30=0,a31=0,a32=0;

    for (int g = gmin; g <= gmax; ++g) {
        const float4* xrow = g_xp + (size_t)(b * 448 + g * S + ri) * PITCH + XOFF + cj;
        const float4* swg  = sw4 + g * G;
#pragma unroll 4
        for (int h = hmin; h <= hmax; ++h) {
            const float4 xv = __ldg(xrow + h * S);
            const float4 wv = swg[h];
            a00 += wv.x * xv.x; a01 += wv.x * xv.y; a02 += wv.x * xv.z;
            a10 += wv.y * xv.x; a11 += wv.y * xv.y; a12 += wv.y * xv.z;
            a20 += wv.z * xv.x; a21 += wv.z * xv.y; a22 += wv.z * xv.z;
            a30 += wv.w * xv.x; a31 += wv.w * xv.y; a32 += wv.w * xv.z;
        }
    }

    float2* dst = g_aggh + (size_t)32 * c_off[cfg] + (size_t)(b * 4) * area + idx;
    __stcs(dst,                    pack_h4(a00, a01, a02));
    __stcs(dst + (size_t)area,     pack_h4(a10, a11, a12));
    __stcs(dst + (size_t)2 * area, pack_h4(a20, a21, a22));
    __stcs(dst + (size_t)3 * area, pack_h4(a30, a31, a32));
}

// ---------------------------------------------------------------------------
// Specialized p5 agg: block-uniform row, unconditional column loads into
// zero guard strips, k-pair packed FFMA2 (6 per tap), 1 LDS.128 per tap.
// grid = (2, 8*373, 9), block = 256.
// ---------------------------------------------------------------------------
__global__ void __launch_bounds__(256) agg5_kernel(const float* __restrict__ w5) {
    const int cfg = 12 + blockIdx.z;
    const int kh = c_kh[cfg], kw = c_kw[cfg];
    const int by = blockIdx.y;
    const int b  = by / 373;
    const int i  = by - b * 373;
    if (i >= kh) return;                      // block-uniform
    const int j0 = blockIdx.x * 256;
    if (j0 >= kw) return;                     // block-uniform

    // swp2[gh] = { (w_k0, w_k1), (w_k2, w_k3) }
    __shared__ ulonglong2 swp2[16];
    {
        const int t = threadIdx.x;
        if (t < 32) {
            const int gh = t >> 1, kp = t & 1;
            const size_t wb = (size_t)(b * 9 + blockIdx.z) * 4;
            const float v0 = w5[(wb + 2 * kp)     * 16 + gh];
            const float v1 = w5[(wb + 2 * kp + 1) * 16 + gh];
            ((unsigned long long*)swp2)[t] = f2pack(v0, v1);
        }
    }
    __syncthreads();

    const int j = j0 + threadIdx.x;
    if (j >= kw) return;

    const int p0 = (kh - 127) >> 1;
    const int p1 = (kw - 127) >> 1;
    const int ri = i - p0;
    const int cj = j - p1;

    // acc[ch][kp], lanes = (k_{2kp}, k_{2kp+1})
    unsigned long long acc[3][2] = {{0ull,0ull},{0ull,0ull},{0ull,0ull}};

    const float4* base = g_xp + ((long long)(b * 448) + ri) * PITCH + XOFF + cj;

#pragma unroll
    for (int g = 0; g < 4; ++g) {
        const int r = g * 128 + ri;
        if ((unsigned)r <= 447u) {            // uniform across block
            float4 xv[4];
#pragma unroll
            for (int h = 0; h < 4; ++h)
                xv[h] = __ldg(base + g * (128 * PITCH) + h * 128);
#pragma unroll
            for (int h = 0; h < 4; ++h) {
                const unsigned long long xx = f2pack(xv[h].x, xv[h].x);
                const unsigned long long xy = f2pack(xv[h].y, xv[h].y);
                const unsigned long long xz = f2pack(xv[h].z, xv[h].z);
                const ulonglong2 w2 = swp2[g * 4 + h];
                ffma2(acc[0][0], w2.x, xx);
                ffma2(acc[1][0], w2.x, xy);
                ffma2(acc[2][0], w2.x, xz);
                ffma2(acc[0][1], w2.y, xx);
                ffma2(acc[1][1], w2.y, xy);
                ffma2(acc[2][1], w2.y, xz);
            }
        }
    }

    const int area = kh * kw;
    float2* dst = g_aggh + (size_t)32 * c_off[cfg] + (size_t)(b * 4) * area
                + (size_t)i * kw + j;
#pragma unroll
    for (int kp = 0; kp < 2; ++kp) {
        float c0a, c0b, c1a, c1b, c2a, c2b;
        funpack(acc[0][kp], c0a, c0b);
        funpack(acc[1][kp], c1a, c1b);
        funpack(acc[2][kp], c2a, c2b);
        __stcs(dst + (size_t)(2 * kp)     * area, pack_h4(c0a, c1a, c2a));
        __stcs(dst + (size_t)(2 * kp + 1) * area, pack_h4(c0b, c1b, c2b));
    }
}

// ---------------------------------------------------------------------------
// Kernel B (R8 version): fully unrolled per-cfg separable resize accumulation.
// ---------------------------------------------------------------------------
template<int AREA, int OFF, int NR, int NC>
__device__ __forceinline__ void do_cfg(int cfg, int bk, int ox,
                                       const float (*s_yw)[4], const int (*s_yo)[4],
                                       float& a0, float& a1, float& a2) {
    const float2* base = g_aggh + (size_t)32 * OFF + (size_t)bk * AREA;
    const float4 xw = g_txw[cfg][ox];
    const int4   xo = g_txo[cfg][ox];
    const float xwv[4] = {xw.x, xw.y, xw.z, xw.w};
    const int   xov[4] = {xo.x, xo.y, xo.z, xo.w};
#pragma unroll
    for (int r = 0; r < NR; ++r) {
        const float wy = s_yw[cfg][r];
        const float2* p = base + s_yo[cfg][r];
#pragma unroll
        for (int c = 0; c < NC; ++c) {
            const float w = wy * xwv[c];
            union { float2 f; __half2 h[2]; } u;
            u.f = __ldg(p + xov[c]);
            const float2 lo = __half22float2(u.h[0]);
            const float  hi = __low2float(u.h[1]);
            a0 += w * lo.x;
            a1 += w * lo.y;
            a2 += w * hi;
        }
    }
}

__global__ void __launch_bounds__(224) resize_kernel(float* __restrict__ out) {
    const int oy = blockIdx.x;
    const int bk = blockIdx.y;
    const int ox = threadIdx.x;

    __shared__ float s_yw[NCFG][4];
    __shared__ int   s_yo[NCFG][4];
    {
        const int t = threadIdx.x;
        if (t < NCFG * 4) {
            const int cfg = t >> 2, k = t & 3;
            s_yw[cfg][k] = ((const float*)&g_tyw[cfg][oy])[k];
            s_yo[cfg][k] = ((const int*)&g_tyo[cfg][oy])[k];
        }
    }
    __syncthreads();

    float a0 = 0.0f, a1 = 0.0f, a2 = 0.0f;

    do_cfg< 3626,      0, 2, 2>( 0, bk, ox, s_yw, s_yo, a0, a1, a2);
    do_cfg< 3600,   3626, 2, 2>( 1, bk, ox, s_yw, s_yo, a0, a1, a2);
    do_cfg< 3626,   7226, 2, 2>( 2, bk, ox, s_yw, s_yo, a0, a1, a2);
    do_cfg< 5766,  10852, 2, 2>( 3, bk, ox, s_yw, s_yo, a0, a1, a2);
    do_cfg< 5776,  16618, 2, 2>( 4, bk, ox, s_yw, s_yo, a0, a1, a2);
    do_cfg< 5766,  22394, 2, 2>( 5, bk, ox, s_yw, s_yo, a0, a1, a2);
    do_cfg<14504,  28160, 2, 2>( 6, bk, ox, s_yw, s_yo, a0, a1, a2);
    do_cfg<14400,  42664, 2, 2>( 7, bk, ox, s_yw, s_yo, a0, a1, a2);
    do_cfg<14504,  57064, 2, 2>( 8, bk, ox, s_yw, s_yo, a0, a1, a2);
    do_cfg<23064,  71568, 2, 2>( 9, bk, ox, s_yw, s_yo, a0, a1, a2);
    do_cfg<23104,  94632, 2, 2>(10, bk, ox, s_yw, s_yo, a0, a1, a2);
    do_cfg<23064, 117736, 2, 2>(11, bk, ox, s_yw, s_yo, a0, a1, a2);
    do_cfg<36660, 140800, 3, 2>(12, bk, ox, s_yw, s_yo, a0, a1, a2);
    do_cfg<36864, 177460, 2, 2>(13, bk, ox, s_yw, s_yo, a0, a1, a2);
    do_cfg<36660, 214324, 2, 3>(14, bk, ox, s_yw, s_yo, a0, a1, a2);
    do_cfg<58312, 250984, 3, 2>(15, bk, ox, s_yw, s_yo, a0, a1, a2);
    do_cfg<58081, 309296, 3, 3>(16, bk, ox, s_yw, s_yo, a0, a1, a2);
    do_cfg<58312, 367377, 2, 3>(17, bk, ox, s_yw, s_yo, a0, a1, a2);
    do_cfg<92504, 425689, 4, 3>(18, bk, ox, s_yw, s_yo, a0, a1, a2);
    do_cfg<92416, 518193, 3, 3>(19, bk, ox, s_yw, s_yo, a0, a1, a2);
    do_cfg<92504, 610609, 3, 4>(20, bk, ox, s_yw, s_yo, a0, a1, a2);

    float* o = out + ((size_t)(bk * 224 + oy) * 224 + ox) * 3;
    o[0] = a0;
    o[1] = a1;
    o[2] = a2;
}

// ---------------------------------------------------------------------------
extern "C" void kernel_launch(void* const* d_in, const int* in_sizes, int n_in,
                              void* d_out, int out_size) {
    const float* x  = (const float*)d_in[0];
    const float* w3 = (const float*)d_in[1];
    const float* w4 = (const float*)d_in[2];
    const float* w5 = (const float*)d_in[3];

    prep_kernel<<<XROWS + 42, 448>>>(x);

    agg_kernel<32, 14, 6, 0><<<dim3(23, 8, 6), 256>>>(w3);
    agg_kernel<64, 7, 6, 6><<<dim3(91, 8, 6), 256>>>(w4);
    agg5_kernel<<<dim3(2, 8 * 373, 9), 256>>>(w5);

    dim3 gridB(224, 32);
    resize_kernel<<<gridB, 224>>>((float*)d_out);
}